// round 1
// baseline (speedup 1.0000x reference)
#include <cuda_runtime.h>
#include <math.h>

#define B      4096
#define T      70
#define NF     101
#define UNITS  125
#define H3     375
#define TS     56      // T - LAG
#define GAMMA  28
#define OUT    202
#define KS     (UNITS*OUT)   // 25250
#define NW     (KS+OUT)      // 25452
#define CC     0.5413248546129181f  // log(expm1(1))

// ---------------- scratch (allocation-free: __device__ globals) ----------------
__device__ float g_Weff[GAMMA][NW];                 // 2.85 MB
__device__ float g_MX[(size_t)TS * B * H3];         // 344 MB: precomputed x@W_k + b0

__device__ __forceinline__ float softplusf(float x) {
    // stable: max(x,0) + log1p(exp(-|x|))
    return fmaxf(x, 0.0f) + log1pf(expf(-fabsf(x)));
}
__device__ __forceinline__ float sigf(float x) {
    return 1.0f / (1.0f + expf(-x));
}

// ---------------- kernel 1: variational weight draws ----------------
__global__ void weff_kernel(const float* __restrict__ dv_loc,
                            const float* __restrict__ dv_rho,
                            const float* __restrict__ eps_w0,
                            const float* __restrict__ eps_w) {
    int idx = blockIdx.x * blockDim.x + threadIdx.x;
    if (idx >= GAMMA * NW) return;
    int g = idx / NW, i = idx - g * NW;
    float eps = (g == 0) ? eps_w0[i] : eps_w[(size_t)(g - 1) * NW + i];
    float sig = 1e-5f + 0.01f * softplusf(CC + dv_rho[i]);
    g_Weff[g][i] = dv_loc[i] + sig * eps;
}

// ---------------- kernel 2: hoisted input projection (all 56 warmup steps) ----
// g_MX[t*B + b][j] = inputs[b, t, :] @ W_k[:, j] + b0[j]
#define MXBM 32
__global__ __launch_bounds__(256) void mx_kernel(const float* __restrict__ inp,
                                                 const float* __restrict__ W_k,
                                                 const float* __restrict__ bias) {
    __shared__ float sx[MXBM][NF + 3];
    int m0 = blockIdx.x * MXBM;
    int tid = threadIdx.x;
    // load x tile: row m = t*B + b  ->  t = m>>12, b = m & 4095 (B = 2^12)
    for (int idx = tid; idx < MXBM * NF; idx += 256) {
        int r = idx / NF, f = idx - r * NF;
        int m = m0 + r;
        int t = m >> 12, bb = m & (B - 1);
        sx[r][f] = inp[((size_t)bb * T + t) * NF + f];
    }
    __syncthreads();
    int grp = tid >> 7;          // 2 row-groups of 16
    int j0  = tid & 127;
    int rb  = grp * 16;
    int j1 = j0 + 128, j2 = j0 + 256;
    bool h2 = (j2 < H3);
    float a0[16], a1[16], a2[16];
#pragma unroll
    for (int i = 0; i < 16; i++) { a0[i] = 0.f; a1[i] = 0.f; a2[i] = 0.f; }
#pragma unroll 2
    for (int k = 0; k < NF; k++) {
        float w0 = __ldg(W_k + k * H3 + j0);
        float w1 = __ldg(W_k + k * H3 + j1);
        float w2 = h2 ? __ldg(W_k + k * H3 + j2) : 0.f;
#pragma unroll
        for (int i = 0; i < 16; i++) {
            float xv = sx[rb + i][k];
            a0[i] = fmaf(xv, w0, a0[i]);
            a1[i] = fmaf(xv, w1, a1[i]);
            a2[i] = fmaf(xv, w2, a2[i]);
        }
    }
    float b0v = bias[j0], b1v = bias[j1], b2v = h2 ? bias[j2] : 0.f;
#pragma unroll
    for (int i = 0; i < 16; i++) {
        size_t row = (size_t)(m0 + rb + i) * H3;
        g_MX[row + j0] = a0[i] + b0v;
        g_MX[row + j1] = a1[i] + b1v;
        if (h2) g_MX[row + j2] = a2[i] + b2v;
    }
}

// ---------------- kernel 3: persistent recurrence, 28 batch rows per CTA ------
#define RTH   512
#define RROWS 28
// smem (floats): h[28][128] | m0[28][376] (mx / y) | m1[28][376] (mi) | x[28][104]
#define SH_H   0
#define SH_MX  (28*128)
#define SH_MI  (SH_MX + 28*376)
#define SH_X   (SH_MI + 28*376)
#define SH_TOT (SH_X + 28*104)        // 27552 floats = 110208 bytes

extern __shared__ float smem[];

__global__ __launch_bounds__(RTH, 1) void rec_kernel(
    const float* __restrict__ W_k, const float* __restrict__ U,
    const float* __restrict__ bias, const float* __restrict__ eps_s,
    float* __restrict__ out)
{
    float* sh_h  = smem + SH_H;
    float* sh_mx = smem + SH_MX;
    float* sh_mi = smem + SH_MI;
    float* sh_x  = smem + SH_X;

    int b0 = blockIdx.x * RROWS;
    if (b0 >= B) return;
    int R = min(RROWS, B - b0);
    int tid = threadIdx.x;

    for (int i = tid; i < 28 * 128; i += RTH) sh_h[i] = 0.f;
    for (int i = tid; i < 28 * 104; i += RTH) sh_x[i] = 0.f;
    __syncthreads();

    int grp = tid >> 8;            // 2 row-groups of 14
    int j0  = tid & 255;
    int rb  = grp * 14;
    int j1  = j0 + 256;
    bool hj1 = (j1 < H3);
    bool hy  = (j0 < OUT);

    // ---------- phase 1: 56 warmup GRU steps (mx precomputed) ----------
    for (int t = 0; t < TS; t++) {
        float acc0[14], acc1[14];
#pragma unroll
        for (int i = 0; i < 14; i++) { acc0[i] = 0.f; acc1[i] = 0.f; }
#pragma unroll 4
        for (int k = 0; k < UNITS; k++) {
            float u0 = __ldg(U + k * H3 + j0);
            float u1 = hj1 ? __ldg(U + k * H3 + j1) : 0.f;
#pragma unroll
            for (int i = 0; i < 14; i++) {
                float hv = sh_h[(rb + i) * 128 + k];
                acc0[i] = fmaf(hv, u0, acc0[i]);
                acc1[i] = fmaf(hv, u1, acc1[i]);
            }
        }
        {
            float bb0 = bias[H3 + j0];
            float bb1 = hj1 ? bias[H3 + j1] : 0.f;
#pragma unroll
            for (int i = 0; i < 14; i++) {
                sh_mi[(rb + i) * 376 + j0] = acc0[i] + bb0;
                if (hj1) sh_mi[(rb + i) * 376 + j1] = acc1[i] + bb1;
            }
        }
        __syncthreads();
        const float* mxg = g_MX + (size_t)t * B * H3 + (size_t)b0 * H3;
        for (int idx = tid; idx < R * UNITS; idx += RTH) {
            int r = idx / UNITS, u = idx - r * UNITS;
            const float* mr = mxg + r * H3;
            const float* mir = sh_mi + r * 376;
            float z  = sigf(mr[u] + mir[u]);
            float rg = sigf(mr[UNITS + u] + mir[UNITS + u]);
            float hh = tanhf(mr[2 * UNITS + u] + rg * mir[2 * UNITS + u]);
            float ho = sh_h[r * 128 + u];
            sh_h[r * 128 + u] = z * ho + (1.f - z) * hh;
        }
        __syncthreads();
    }

    // ---------- phase 2: 28 dense draws + 27 feedback GRU steps ----------
    for (int g = 0; g < GAMMA; g++) {
        const float* Wg = g_Weff[g];
        // y = h @ kernel + bias  -> sh_mx[r][0..201]
        if (hy) {
            float acc[14];
#pragma unroll
            for (int i = 0; i < 14; i++) acc[i] = 0.f;
#pragma unroll 4
            for (int k = 0; k < UNITS; k++) {
                float wv = __ldg(Wg + k * OUT + j0);
#pragma unroll
                for (int i = 0; i < 14; i++)
                    acc[i] = fmaf(sh_h[(rb + i) * 128 + k], wv, acc[i]);
            }
            float bv = Wg[KS + j0];
#pragma unroll
            for (int i = 0; i < 14; i++)
                sh_mx[(rb + i) * 376 + j0] = acc[i] + bv;
        }
        __syncthreads();
        // dist params -> output + feedback x
        for (int idx = tid; idx < R * NF; idx += RTH) {
            int r = idx / NF, f = idx - r * NF;
            float loc = sh_mx[r * 376 + f];
            float sc  = 1e-5f + 0.05f * softplusf(CC + sh_mx[r * 376 + NF + f]);
            size_t ob = ((size_t)(b0 + r) * GAMMA + g) * OUT;
            out[ob + f]      = loc;
            out[ob + NF + f] = sc;
            if (g < GAMMA - 1) {
                float es = eps_s[((size_t)g * B + (b0 + r)) * NF + f];
                sh_x[r * 104 + f] = loc + sc * es;
            }
        }
        __syncthreads();
        if (g == GAMMA - 1) break;

        // mx = x @ W_k + b0   (overwrites y region; readers synced above)
        float acc0[14], acc1[14];
#pragma unroll
        for (int i = 0; i < 14; i++) { acc0[i] = 0.f; acc1[i] = 0.f; }
#pragma unroll 4
        for (int k = 0; k < NF; k++) {
            float w0 = __ldg(W_k + k * H3 + j0);
            float w1 = hj1 ? __ldg(W_k + k * H3 + j1) : 0.f;
#pragma unroll
            for (int i = 0; i < 14; i++) {
                float xv = sh_x[(rb + i) * 104 + k];
                acc0[i] = fmaf(xv, w0, acc0[i]);
                acc1[i] = fmaf(xv, w1, acc1[i]);
            }
        }
        {
            float bb0 = bias[j0];
            float bb1 = hj1 ? bias[j1] : 0.f;
#pragma unroll
            for (int i = 0; i < 14; i++) {
                sh_mx[(rb + i) * 376 + j0] = acc0[i] + bb0;
                if (hj1) sh_mx[(rb + i) * 376 + j1] = acc1[i] + bb1;
            }
        }
        // mi = h @ U + b1
#pragma unroll
        for (int i = 0; i < 14; i++) { acc0[i] = 0.f; acc1[i] = 0.f; }
#pragma unroll 4
        for (int k = 0; k < UNITS; k++) {
            float u0 = __ldg(U + k * H3 + j0);
            float u1 = hj1 ? __ldg(U + k * H3 + j1) : 0.f;
#pragma unroll
            for (int i = 0; i < 14; i++) {
                float hv = sh_h[(rb + i) * 128 + k];
                acc0[i] = fmaf(hv, u0, acc0[i]);
                acc1[i] = fmaf(hv, u1, acc1[i]);
            }
        }
        {
            float bb0 = bias[H3 + j0];
            float bb1 = hj1 ? bias[H3 + j1] : 0.f;
#pragma unroll
            for (int i = 0; i < 14; i++) {
                sh_mi[(rb + i) * 376 + j0] = acc0[i] + bb0;
                if (hj1) sh_mi[(rb + i) * 376 + j1] = acc1[i] + bb1;
            }
        }
        __syncthreads();
        // GRU elementwise update
        for (int idx = tid; idx < R * UNITS; idx += RTH) {
            int r = idx / UNITS, u = idx - r * UNITS;
            const float* mxr = sh_mx + r * 376;
            const float* mir = sh_mi + r * 376;
            float z  = sigf(mxr[u] + mir[u]);
            float rg = sigf(mxr[UNITS + u] + mir[UNITS + u]);
            float hh = tanhf(mxr[2 * UNITS + u] + rg * mir[2 * UNITS + u]);
            float ho = sh_h[r * 128 + u];
            sh_h[r * 128 + u] = z * ho + (1.f - z) * hh;
        }
        __syncthreads();
    }
}

// ---------------- launch ----------------
extern "C" void kernel_launch(void* const* d_in, const int* in_sizes, int n_in,
                              void* d_out, int out_size) {
    const float* inputs = (const float*)d_in[0];
    const float* W_k    = (const float*)d_in[1];
    const float* U      = (const float*)d_in[2];
    const float* b      = (const float*)d_in[3];
    const float* dv_loc = (const float*)d_in[4];
    const float* dv_rho = (const float*)d_in[5];
    const float* eps_w0 = (const float*)d_in[6];
    const float* eps_w  = (const float*)d_in[7];
    const float* eps_s  = (const float*)d_in[8];
    float* out = (float*)d_out;

    weff_kernel<<<(GAMMA * NW + 255) / 256, 256>>>(dv_loc, dv_rho, eps_w0, eps_w);
    mx_kernel<<<(TS * B) / MXBM, 256>>>(inputs, W_k, b);

    cudaFuncSetAttribute(rec_kernel, cudaFuncAttributeMaxDynamicSharedMemorySize,
                         SH_TOT * (int)sizeof(float));
    rec_kernel<<<(B + RROWS - 1) / RROWS, RTH, SH_TOT * sizeof(float)>>>(
        W_k, U, b, eps_s, out);
}

// round 3
// speedup vs baseline: 1.5920x; 1.5920x over previous
#include <cuda_runtime.h>
#include <math.h>

#define B      4096
#define T      70
#define NF     101
#define UNITS  125
#define H3     375
#define H3P    384
#define TS     56      // T - LAG
#define GAMMA  28
#define OUT    202
#define KS     (UNITS*OUT)   // 25250
#define NW     (KS+OUT)      // 25452
#define CC     0.5413248546129181f  // log(expm1(1))
#define RROWS  28
#define RTH    384
#define MXS    385           // row stride (floats) for MX/MI buffers (odd -> conflict-free)
#define XS     36            // k-stride for X buffer ([k][slot])
#define HS     32            // k-stride for H buffer ([u][slot])

typedef unsigned long long ull;

// ---------------- padded weights in __device__ globals (no allocs) ------------
__device__ float g_Wkp[NF * H3P];            // W_k zero-padded to [101][384]
__device__ float g_Up [UNITS * H3P];         // U   zero-padded to [125][384]
__device__ float g_b0p[H3P];
__device__ float g_b1p[H3P];
__device__ float g_Wf [(size_t)GAMMA * UNITS * H3P];  // variational kernels [g][125][384]
__device__ float g_Wfb[GAMMA * H3P];                  // variational biases  [g][384]

// ---------------- helpers -----------------------------------------------------
__device__ __forceinline__ ull pk2(float lo, float hi) {
    ull r; asm("mov.b64 %0, {%1,%2};" : "=l"(r) : "f"(lo), "f"(hi)); return r;
}
__device__ __forceinline__ float2 upk(ull v) {
    float2 r; asm("mov.b64 {%0,%1}, %2;" : "=f"(r.x), "=f"(r.y) : "l"(v)); return r;
}
__device__ __forceinline__ void fma2(ull& d, ull a, ull b) {
    asm("fma.rn.f32x2 %0, %1, %2, %3;" : "=l"(d) : "l"(a), "l"(b), "l"(d));
}
__device__ __forceinline__ float sigf(float x) {
    return __fdividef(1.f, 1.f + __expf(-x));
}
__device__ __forceinline__ float tanhfast(float x) {
    float e = __expf(-2.f * x);
    return __fdividef(1.f - e, 1.f + e);
}
__device__ __forceinline__ float splus(float x) {
    return fmaxf(x, 0.f) + __logf(1.f + __expf(-fabsf(x)));
}

// ---------------- kernel A: pad W_k / U / b -----------------------------------
__global__ void pad_kernel(const float* __restrict__ W_k,
                           const float* __restrict__ U,
                           const float* __restrict__ bvec) {
    int idx = blockIdx.x * blockDim.x + threadIdx.x;
    if (idx < NF * H3P) {
        int k = idx / H3P, j = idx - k * H3P;
        g_Wkp[idx] = (j < H3) ? W_k[k * H3 + j] : 0.f;
    } else if (idx < (NF + UNITS) * H3P) {
        int i2 = idx - NF * H3P;
        int k = i2 / H3P, j = i2 - k * H3P;
        g_Up[i2] = (j < H3) ? U[k * H3 + j] : 0.f;
    } else if (idx < (NF + UNITS) * H3P + H3P) {
        int j = idx - (NF + UNITS) * H3P;
        g_b0p[j] = (j < H3) ? bvec[j] : 0.f;
    } else if (idx < (NF + UNITS) * H3P + 2 * H3P) {
        int j = idx - (NF + UNITS) * H3P - H3P;
        g_b1p[j] = (j < H3) ? bvec[H3 + j] : 0.f;
    }
}

// ---------------- kernel B: variational weight draws (padded layout) ----------
__global__ void weff_kernel(const float* __restrict__ loc,
                            const float* __restrict__ rho,
                            const float* __restrict__ ew0,
                            const float* __restrict__ ew) {
    int idx = blockIdx.x * blockDim.x + threadIdx.x;
    const int total_k = GAMMA * UNITS * H3P;
    if (idx < total_k) {
        int g = idx / (UNITS * H3P);
        int rem = idx - g * (UNITS * H3P);
        int k = rem / H3P, j = rem - k * H3P;
        float v = 0.f;
        if (j < OUT) {
            int i = k * OUT + j;
            float e = g ? ew[(size_t)(g - 1) * NW + i] : ew0[i];
            v = fmaf(1e-5f + 0.01f * splus(CC + rho[i]), e, loc[i]);
        }
        g_Wf[idx] = v;
    } else {
        idx -= total_k;
        if (idx >= GAMMA * H3P) return;
        int g = idx / H3P, j = idx - g * H3P;
        float v = 0.f;
        if (j < OUT) {
            int i = KS + j;
            float e = g ? ew[(size_t)(g - 1) * NW + i] : ew0[i];
            v = fmaf(1e-5f + 0.01f * splus(CC + rho[i]), e, loc[i]);
        }
        g_Wfb[g * H3P + j] = v;
    }
}

// ---------------- packed-FMA tile GEMM: dst[slot][j] = src[:,slot] . W[:,j] + b[j]
// src layout: [k][slot-stride SS]; row-pairs loaded as 64/128-bit LDS (packed).
template<int K, int SS>
__device__ __forceinline__ void gemm_step(const float* __restrict__ W,
                                          const float* __restrict__ bias,
                                          const float* __restrict__ src,
                                          float* __restrict__ dst,
                                          int rb, int j0, int j1) {
    ull a[14];
    {
        float bb0 = bias[j0], bb1 = bias[j1];
        ull pb0 = pk2(bb0, bb0), pb1 = pk2(bb1, bb1);
#pragma unroll
        for (int i = 0; i < 7; i++) { a[i] = pb0; a[7 + i] = pb1; }
    }
#pragma unroll 4
    for (int k = 0; k < K; k++) {
        const float* s = src + k * SS + rb;
        ulonglong2 q0 = *(const ulonglong2*)(s);       // slots rb+0..3 (2 pairs)
        ull p2 = *(const ull*)(s + 4);                 // slots rb+4,5
        ull p3 = *(const ull*)(s + 6);                 // slots rb+6,7
        ulonglong2 q2 = *(const ulonglong2*)(s + 8);   // slots rb+8..11
        ull p6 = *(const ull*)(s + 12);                // slots rb+12,13
        float w0 = W[k * H3P + j0];
        float w1 = W[k * H3P + j1];
        ull u0 = pk2(w0, w0), u1 = pk2(w1, w1);
        fma2(a[0], q0.x, u0);  fma2(a[1], q0.y, u0);
        fma2(a[2], p2,  u0);   fma2(a[3], p3,  u0);
        fma2(a[4], q2.x, u0);  fma2(a[5], q2.y, u0);
        fma2(a[6], p6,  u0);
        fma2(a[7],  q0.x, u1); fma2(a[8],  q0.y, u1);
        fma2(a[9],  p2,  u1);  fma2(a[10], p3,  u1);
        fma2(a[11], q2.x, u1); fma2(a[12], q2.y, u1);
        fma2(a[13], p6,  u1);
    }
#pragma unroll
    for (int i = 0; i < 7; i++) {
        float2 v0 = upk(a[i]), v1 = upk(a[7 + i]);
        int r0 = rb + 2 * i;
        dst[r0 * MXS + j0]       = v0.x;
        dst[(r0 + 1) * MXS + j0] = v0.y;
        dst[r0 * MXS + j1]       = v1.x;
        dst[(r0 + 1) * MXS + j1] = v1.y;
    }
}

// ---------------- main persistent recurrence ----------------------------------
// smem layout (floats)
#define SM_H   0
#define SM_MX  (UNITS * HS)                 // 4000
#define SM_MI  (SM_MX + 32 * MXS)           // + 12320
#define SM_X   (SM_MI + 32 * MXS)           // + 12320
#define SM_TOT (SM_X + NF * XS)             // + 3636 = 32276 floats = 129104 B

extern __shared__ float smem[];

__global__ __launch_bounds__(RTH, 1) void rec_kernel(
    const float* __restrict__ inp, const float* __restrict__ eps_s,
    float* __restrict__ out)
{
    float* sH  = smem + SM_H;
    float* sMX = smem + SM_MX;
    float* sMI = smem + SM_MI;
    float* sX  = smem + SM_X;

    int b0 = blockIdx.x * RROWS;
    int R = min(RROWS, B - b0);
    int tid = threadIdx.x;
    int grp = (tid >= 192);
    int rb = grp ? 16 : 0;                  // slot base (16-aligned for LDS.128)
    int j0 = tid - (grp ? 192 : 0);         // 0..191
    int j1 = j0 + 192;                      // 192..383

    for (int i = tid; i < UNITS * HS; i += RTH) sH[i] = 0.f;
    for (int i = tid; i < NF * XS; i += RTH)    sX[i] = 0.f;
    __syncthreads();

    // ---------- phase 1: 56 warmup GRU steps (x from inputs) ----------
    for (int t = 0; t < TS; t++) {
        // stage x tile (coalesced global read, 4-way-conflict smem write — tiny)
        for (int idx = tid; idx < R * NF; idx += RTH) {
            int r = idx / NF, f = idx - r * NF;
            int s = r + (r >= 14 ? 2 : 0);
            sX[f * XS + s] = inp[((size_t)(b0 + r) * T + t) * NF + f];
        }
        __syncthreads();
        gemm_step<NF, XS>(g_Wkp, g_b0p, sX, sMX, rb, j0, j1);
        gemm_step<UNITS, HS>(g_Up, g_b1p, sH, sMI, rb, j0, j1);
        __syncthreads();
        // GRU elementwise (slot-fastest: conflict-free h writes)
        for (int idx = tid; idx < HS * UNITS; idx += RTH) {
            int s = idx & 31, u = idx >> 5;
            if (s == 14 || s == 15 || s >= 30) continue;
            const float* mx = sMX + s * MXS;
            const float* mi = sMI + s * MXS;
            float z  = sigf(mx[u] + mi[u]);
            float rg = sigf(mx[UNITS + u] + mi[UNITS + u]);
            float hh = tanhfast(fmaf(rg, mi[2 * UNITS + u], mx[2 * UNITS + u]));
            float ho = sH[u * HS + s];
            sH[u * HS + s] = z * ho + (1.f - z) * hh;
        }
        __syncthreads();
    }

    // ---------- phase 2: 28 dense draws + 27 feedback GRU steps ----------
    for (int g = 0; g < GAMMA; g++) {
        // y = h @ Wf[g] + bf[g]   -> sMX
        gemm_step<UNITS, HS>(g_Wf + (size_t)g * UNITS * H3P, g_Wfb + g * H3P,
                             sH, sMX, rb, j0, j1);
        __syncthreads();
        // dist params -> output (coalesced) + feedback x
        for (int idx = tid; idx < R * NF; idx += RTH) {
            int r = idx / NF, f = idx - r * NF;
            int s = r + (r >= 14 ? 2 : 0);
            float loc = sMX[s * MXS + f];
            float sc  = 1e-5f + 0.05f * splus(CC + sMX[s * MXS + NF + f]);
            size_t ob = ((size_t)(b0 + r) * GAMMA + g) * OUT;
            out[ob + f]      = loc;
            out[ob + NF + f] = sc;
            if (g < GAMMA - 1) {
                float es = eps_s[((size_t)g * B + b0 + r) * NF + f];
                sX[f * XS + s] = fmaf(sc, es, loc);
            }
        }
        __syncthreads();
        if (g == GAMMA - 1) break;

        gemm_step<NF, XS>(g_Wkp, g_b0p, sX, sMX, rb, j0, j1);   // overwrites y
        gemm_step<UNITS, HS>(g_Up, g_b1p, sH, sMI, rb, j0, j1);
        __syncthreads();
        for (int idx = tid; idx < HS * UNITS; idx += RTH) {
            int s = idx & 31, u = idx >> 5;
            if (s == 14 || s == 15 || s >= 30) continue;
            const float* mx = sMX + s * MXS;
            const float* mi = sMI + s * MXS;
            float z  = sigf(mx[u] + mi[u]);
            float rg = sigf(mx[UNITS + u] + mi[UNITS + u]);
            float hh = tanhfast(fmaf(rg, mi[2 * UNITS + u], mx[2 * UNITS + u]));
            float ho = sH[u * HS + s];
            sH[u * HS + s] = z * ho + (1.f - z) * hh;
        }
        __syncthreads();
    }
}

// ---------------- launch ------------------------------------------------------
extern "C" void kernel_launch(void* const* d_in, const int* in_sizes, int n_in,
                              void* d_out, int out_size) {
    const float* inputs = (const float*)d_in[0];
    const float* W_k    = (const float*)d_in[1];
    const float* U      = (const float*)d_in[2];
    const float* b      = (const float*)d_in[3];
    const float* dv_loc = (const float*)d_in[4];
    const float* dv_rho = (const float*)d_in[5];
    const float* eps_w0 = (const float*)d_in[6];
    const float* eps_w  = (const float*)d_in[7];
    const float* eps_s  = (const float*)d_in[8];
    float* out = (float*)d_out;

    int total_pad = (NF + UNITS) * H3P + 2 * H3P;
    pad_kernel<<<(total_pad + 255) / 256, 256>>>(W_k, U, b);

    int total_w = GAMMA * (UNITS + 1) * H3P;
    weff_kernel<<<(total_w + 255) / 256, 256>>>(dv_loc, dv_rho, eps_w0, eps_w);

    cudaFuncSetAttribute(rec_kernel, cudaFuncAttributeMaxDynamicSharedMemorySize,
                         SM_TOT * (int)sizeof(float));
    rec_kernel<<<(B + RROWS - 1) / RROWS, RTH, SM_TOT * sizeof(float)>>>(
        inputs, eps_s, out);
}

// round 4
// speedup vs baseline: 2.0034x; 1.2584x over previous
#include <cuda_runtime.h>
#include <math.h>

#define B      4096
#define T      70
#define NF     101
#define NFP    104           // padded K for x@W_k (mult of 8)
#define UNITS  125
#define UP     128           // padded K for h@U / h@Wf (mult of 8)
#define H3     375
#define H3P    384
#define TS     56            // T - LAG
#define GAMMA  28
#define OUT    202
#define KS     (UNITS*OUT)   // 25250
#define NW     (KS+OUT)      // 25452
#define CC     0.5413248546129181f
#define RROWS  28
#define RTH    384
#define MXS    385           // odd row stride for MX/MI (conflict-free)
#define XS     36            // k-stride for X [k][slot] (mult of 4)
#define HS     32            // k-stride for H [u][slot]
#define PADR   8             // OOB-safe prefetch pad rows

typedef unsigned long long ull;

// ---------------- padded weights in __device__ globals ------------------------
__device__ float g_Wkp[(NFP + PADR) * H3P];
__device__ float g_Up [(UP  + PADR) * H3P];
__device__ float g_b0p[H3P];
__device__ float g_b1p[H3P];
__device__ float g_Wf [(size_t)GAMMA * UP * H3P + PADR * H3P];
__device__ float g_Wfb[GAMMA * H3P];

// ---------------- helpers -----------------------------------------------------
__device__ __forceinline__ ull pk2(float lo, float hi) {
    ull r; asm("mov.b64 %0, {%1,%2};" : "=l"(r) : "f"(lo), "f"(hi)); return r;
}
__device__ __forceinline__ float2 upk(ull v) {
    float2 r; asm("mov.b64 {%0,%1}, %2;" : "=f"(r.x), "=f"(r.y) : "l"(v)); return r;
}
__device__ __forceinline__ void fma2(ull& d, ull a, ull b) {
    asm("fma.rn.f32x2 %0, %1, %2, %3;" : "=l"(d) : "l"(a), "l"(b), "l"(d));
}
__device__ __forceinline__ float sigf(float x) {
    return __fdividef(1.f, 1.f + __expf(-x));
}
__device__ __forceinline__ float tanhfast(float x) {
    float e = __expf(-2.f * x);
    return __fdividef(1.f - e, 1.f + e);
}
__device__ __forceinline__ float splus(float x) {
    return fmaxf(x, 0.f) + __logf(1.f + __expf(-fabsf(x)));
}

// ---------------- prep kernel: pad weights + variational draws ----------------
#define R1 (NFP * H3P)
#define R2 (R1 + UP * H3P)
#define R3 (R2 + H3P)
#define R4 (R3 + H3P)
#define R5 (R4 + GAMMA * UP * H3P)
#define R6 (R5 + GAMMA * H3P)

__global__ void prep_kernel(const float* __restrict__ W_k,
                            const float* __restrict__ U,
                            const float* __restrict__ bvec,
                            const float* __restrict__ loc,
                            const float* __restrict__ rho,
                            const float* __restrict__ ew0,
                            const float* __restrict__ ew) {
    int idx = blockIdx.x * blockDim.x + threadIdx.x;
    if (idx < R1) {
        int k = idx / H3P, j = idx - k * H3P;
        g_Wkp[idx] = (j < H3 && k < NF) ? W_k[k * H3 + j] : 0.f;
    } else if (idx < R2) {
        int i2 = idx - R1;
        int k = i2 / H3P, j = i2 - k * H3P;
        g_Up[i2] = (j < H3 && k < UNITS) ? U[k * H3 + j] : 0.f;
    } else if (idx < R3) {
        int j = idx - R2;
        g_b0p[j] = (j < H3) ? bvec[j] : 0.f;
    } else if (idx < R4) {
        int j = idx - R3;
        g_b1p[j] = (j < H3) ? bvec[H3 + j] : 0.f;
    } else if (idx < R5) {
        int i2 = idx - R4;
        int g = i2 / (UP * H3P);
        int rem = i2 - g * (UP * H3P);
        int k = rem / H3P, j = rem - k * H3P;
        float v = 0.f;
        if (j < OUT && k < UNITS) {
            int i = k * OUT + j;
            float e = g ? ew[(size_t)(g - 1) * NW + i] : ew0[i];
            v = fmaf(1e-5f + 0.01f * splus(CC + rho[i]), e, loc[i]);
        }
        g_Wf[i2] = v;
    } else if (idx < R6) {
        int i2 = idx - R5;
        int g = i2 / H3P, j = i2 - g * H3P;
        float v = 0.f;
        if (j < OUT) {
            int i = KS + j;
            float e = g ? ew[(size_t)(g - 1) * NW + i] : ew0[i];
            v = fmaf(1e-5f + 0.01f * splus(CC + rho[i]), e, loc[i]);
        }
        g_Wfb[i2] = v;
    }
}

// ---------------- 4-k chunk of packed FMAs ------------------------------------
template<int SS>
__device__ __forceinline__ void chunk4(ull (&a)[14], const float* __restrict__ src,
                                       int rb, const float* wa, const float* wb) {
#pragma unroll
    for (int c = 0; c < 4; c++) {
        const float* s = src + c * SS + rb;
        ulonglong2 q0 = *(const ulonglong2*)(s);
        ulonglong2 q1 = *(const ulonglong2*)(s + 4);
        ulonglong2 q2 = *(const ulonglong2*)(s + 8);
        ull p6 = *(const ull*)(s + 12);
        ull u0 = pk2(wa[c], wa[c]);
        ull u1 = pk2(wb[c], wb[c]);
        fma2(a[0], q0.x, u0);  fma2(a[1], q0.y, u0);
        fma2(a[2], q1.x, u0);  fma2(a[3], q1.y, u0);
        fma2(a[4], q2.x, u0);  fma2(a[5], q2.y, u0);
        fma2(a[6], p6,  u0);
        fma2(a[7],  q0.x, u1); fma2(a[8],  q0.y, u1);
        fma2(a[9],  q1.x, u1); fma2(a[10], q1.y, u1);
        fma2(a[11], q2.x, u1); fma2(a[12], q2.y, u1);
        fma2(a[13], p6,  u1);
    }
}

// ---------------- tile GEMM with ping-pong weight prefetch --------------------
// dst[slot][j] = sum_k src[k][slot] * W[k][j] + bias[j]; KP mult of 8.
template<int KP, int SS>
__device__ __forceinline__ void gemm_step(const float* __restrict__ W,
                                          const float* __restrict__ bias,
                                          const float* __restrict__ src,
                                          float* __restrict__ dst,
                                          int rb, int j0, int j1) {
    ull a[14];
    {
        float bb0 = bias[j0], bb1 = bias[j1];
        ull pb0 = pk2(bb0, bb0), pb1 = pk2(bb1, bb1);
#pragma unroll
        for (int i = 0; i < 7; i++) { a[i] = pb0; a[7 + i] = pb1; }
    }
    float wa0[4], wb0[4], wa1[4], wb1[4];
#pragma unroll
    for (int c = 0; c < 4; c++) {
        wa0[c] = W[c * H3P + j0];       wb0[c] = W[c * H3P + j1];
        wa1[c] = W[(4 + c) * H3P + j0]; wb1[c] = W[(4 + c) * H3P + j1];
    }
#pragma unroll 1
    for (int kc = 0; kc < KP; kc += 8) {
        const float* Wn = W + (size_t)(kc + 8) * H3P;
        chunk4<SS>(a, src + kc * SS, rb, wa0, wb0);
#pragma unroll
        for (int c = 0; c < 4; c++) { wa0[c] = Wn[c * H3P + j0]; wb0[c] = Wn[c * H3P + j1]; }
        chunk4<SS>(a, src + (kc + 4) * SS, rb, wa1, wb1);
#pragma unroll
        for (int c = 0; c < 4; c++) { wa1[c] = Wn[(4 + c) * H3P + j0]; wb1[c] = Wn[(4 + c) * H3P + j1]; }
    }
#pragma unroll
    for (int i = 0; i < 7; i++) {
        float2 v0 = upk(a[i]), v1 = upk(a[7 + i]);
        int r0 = rb + 2 * i;
        dst[r0 * MXS + j0]       = v0.x;
        dst[(r0 + 1) * MXS + j0] = v0.y;
        dst[r0 * MXS + j1]       = v1.x;
        dst[(r0 + 1) * MXS + j1] = v1.y;
    }
}

// ---------------- main persistent recurrence ----------------------------------
#define SM_H   0
#define SM_MX  (UP * HS)                   // 4096
#define SM_MI  (SM_MX + 32 * MXS)          // + 12320
#define SM_X   (SM_MI + 32 * MXS)          // + 12320
#define SM_TOT (SM_X + NFP * XS)           // + 3744 = 32480 floats = 129920 B

extern __shared__ float smem[];

__global__ __launch_bounds__(RTH, 1) void rec_kernel(
    const float* __restrict__ inp, const float* __restrict__ eps_s,
    float* __restrict__ out)
{
    float* sH  = smem + SM_H;
    float* sMX = smem + SM_MX;
    float* sMI = smem + SM_MI;
    float* sX  = smem + SM_X;

    int b0 = blockIdx.x * RROWS;
    int R = min(RROWS, B - b0);
    int tid = threadIdx.x;
    int grp = (tid >= 192);
    int rb = grp ? 16 : 0;
    int j0 = tid - (grp ? 192 : 0);
    int j1 = j0 + 192;

    for (int i = tid; i < UP * HS; i += RTH)  sH[i] = 0.f;
    for (int i = tid; i < NFP * XS; i += RTH) sX[i] = 0.f;

    float xr[8];
    // preload x(t=0)
    {
        int i = 0;
        for (int idx = tid; idx < R * NF; idx += RTH, i++)
            xr[i] = inp[((size_t)(b0 + idx / NF) * T + 0) * NF + (idx % NF)];
    }
    __syncthreads();
    {
        int i = 0;
        for (int idx = tid; idx < R * NF; idx += RTH, i++) {
            int r = idx / NF, f = idx - r * NF;
            int s = r + (r >= 14 ? 2 : 0);
            sX[f * XS + s] = xr[i];
        }
    }
    __syncthreads();

    // ---------- phase 1: 56 warmup GRU steps ----------
    for (int t = 0; t < TS; t++) {
        // issue x(t+1) global loads (hidden behind GEMMs)
        if (t + 1 < TS) {
            int i = 0;
            for (int idx = tid; idx < R * NF; idx += RTH, i++)
                xr[i] = inp[((size_t)(b0 + idx / NF) * T + (t + 1)) * NF + (idx % NF)];
        }
        gemm_step<NFP, XS>(g_Wkp, g_b0p, sX, sMX, rb, j0, j1);
        gemm_step<UP,  HS>(g_Up,  g_b1p, sH, sMI, rb, j0, j1);
        __syncthreads();
        // GRU elementwise
        for (int idx = tid; idx < RROWS * UNITS; idx += RTH) {
            int s28 = idx % RROWS, u = idx / RROWS;
            int s = s28 + (s28 >= 14 ? 2 : 0);
            const float* mx = sMX + s * MXS;
            const float* mi = sMI + s * MXS;
            float z  = sigf(mx[u] + mi[u]);
            float rg = sigf(mx[UNITS + u] + mi[UNITS + u]);
            float hh = tanhfast(fmaf(rg, mi[2 * UNITS + u], mx[2 * UNITS + u]));
            float ho = sH[u * HS + s];
            sH[u * HS + s] = z * ho + (1.f - z) * hh;
        }
        // publish x(t+1)
        if (t + 1 < TS) {
            int i = 0;
            for (int idx = tid; idx < R * NF; idx += RTH, i++) {
                int r = idx / NF, f = idx - r * NF;
                int s = r + (r >= 14 ? 2 : 0);
                sX[f * XS + s] = xr[i];
            }
        }
        __syncthreads();
    }

    // ---------- phase 2: 28 dense draws + 27 feedback GRU steps ----------
    for (int g = 0; g < GAMMA; g++) {
        // issue eps_s(g) loads (hidden behind dense GEMM)
        if (g < GAMMA - 1) {
            int i = 0;
            for (int idx = tid; idx < R * NF; idx += RTH, i++)
                xr[i] = eps_s[((size_t)g * B + b0 + idx / NF) * NF + (idx % NF)];
        }
        // y = h @ Wf[g] + bf[g] -> sMI
        gemm_step<UP, HS>(g_Wf + (size_t)g * UP * H3P, g_Wfb + g * H3P,
                          sH, sMI, rb, j0, j1);
        __syncthreads();
        // dist params -> output + feedback x
        {
            int i = 0;
            for (int idx = tid; idx < R * NF; idx += RTH, i++) {
                int r = idx / NF, f = idx - r * NF;
                int s = r + (r >= 14 ? 2 : 0);
                float loc = sMI[s * MXS + f];
                float sc  = 1e-5f + 0.05f * splus(CC + sMI[s * MXS + NF + f]);
                size_t ob = ((size_t)(b0 + r) * GAMMA + g) * OUT;
                out[ob + f]      = loc;
                out[ob + NF + f] = sc;
                if (g < GAMMA - 1) sX[f * XS + s] = fmaf(sc, xr[i], loc);
            }
        }
        __syncthreads();
        if (g == GAMMA - 1) break;

        gemm_step<NFP, XS>(g_Wkp, g_b0p, sX, sMX, rb, j0, j1);
        gemm_step<UP,  HS>(g_Up,  g_b1p, sH, sMI, rb, j0, j1);
        __syncthreads();
        for (int idx = tid; idx < RROWS * UNITS; idx += RTH) {
            int s28 = idx % RROWS, u = idx / RROWS;
            int s = s28 + (s28 >= 14 ? 2 : 0);
            const float* mx = sMX + s * MXS;
            const float* mi = sMI + s * MXS;
            float z  = sigf(mx[u] + mi[u]);
            float rg = sigf(mx[UNITS + u] + mi[UNITS + u]);
            float hh = tanhfast(fmaf(rg, mi[2 * UNITS + u], mx[2 * UNITS + u]));
            float ho = sH[u * HS + s];
            sH[u * HS + s] = z * ho + (1.f - z) * hh;
        }
        __syncthreads();
    }
}

// ---------------- launch ------------------------------------------------------
extern "C" void kernel_launch(void* const* d_in, const int* in_sizes, int n_in,
                              void* d_out, int out_size) {
    const float* inputs = (const float*)d_in[0];
    const float* W_k    = (const float*)d_in[1];
    const float* U      = (const float*)d_in[2];
    const float* b      = (const float*)d_in[3];
    const float* dv_loc = (const float*)d_in[4];
    const float* dv_rho = (const float*)d_in[5];
    const float* eps_w0 = (const float*)d_in[6];
    const float* eps_w  = (const float*)d_in[7];
    const float* eps_s  = (const float*)d_in[8];
    float* out = (float*)d_out;

    prep_kernel<<<(R6 + 255) / 256, 256>>>(W_k, U, b, dv_loc, dv_rho, eps_w0, eps_w);

    cudaFuncSetAttribute(rec_kernel, cudaFuncAttributeMaxDynamicSharedMemorySize,
                         SM_TOT * (int)sizeof(float));
    rec_kernel<<<(B + RROWS - 1) / RROWS, RTH, SM_TOT * sizeof(float)>>>(
        inputs, eps_s, out);
}